// round 3
// baseline (speedup 1.0000x reference)
#include <cuda_runtime.h>
#include <cuda_bf16.h>
#include <math.h>
#include <complex>
#include <algorithm>

// ---------------- static problem shape ----------------
#define MUL    16
#define NCFG   64
#define NATOM  64
#define NNODES 4096
#define NPAIRS 262144

// ---------------- device scratch (no allocation allowed) ----------------
__device__ float g_C[(size_t)NNODES * 1296];   // C[node][kg(9)][b2(144)]   ~21 MB
__device__ float g_irr[(size_t)NPAIRS * 9];    // irr[pair][9]              ~9.4 MB

// ---------------- compile-time path structure tables (device) ----------------
// PATHS order: p0(0,0,0) p1(1,1,0) p2(2,2,0) p3(0,1,1) p4(1,0,1) p5(1,1,1)
//  p6(1,2,1) p7(2,1,1) p8(2,2,1) p9(0,2,2) p10(2,0,2) p11(1,1,2) p12(1,2,2)
//  p13(2,1,2) p14(2,2,2)
__constant__ int A_P[51] = {
  0, 1,1,1, 2,2,2,2,2, 3, 4,4,4, 5,5,5, 6,6,6,
  7,7,7,7,7, 8,8,8,8,8, 9, 10,10,10,10,10,
  11,11,11, 12,12,12, 13,13,13,13,13, 14,14,14,14,14 };
__constant__ int A_FB[51] = {
  0, 16,17,18, 64,65,66,67,68, 0, 16,17,18, 16,17,18, 16,17,18,
  64,65,66,67,68, 64,65,66,67,68, 0, 64,65,66,67,68,
  16,17,18, 16,17,18, 64,65,66,67,68, 64,65,66,67,68 };
__constant__ int A_ST[51] = {
  1, 3,3,3, 5,5,5,5,5, 1, 3,3,3, 3,3,3, 3,3,3,
  5,5,5,5,5, 5,5,5,5,5, 1, 5,5,5,5,5,
  3,3,3, 3,3,3, 5,5,5,5,5, 5,5,5,5,5 };

__constant__ int P_TOFF[15]  = {0,1,4,9,10,13,16,19,24,29,30,35,38,41,46};
__constant__ int P_W3OFF[15] = {0,1,10,35,44,53,80,125,170,245,270,295,340,415,490};
__constant__ int P_IDIM[15]  = {1,3,5,1,3,3,3,5,5,1,5,3,3,5,5};
// paths contributing to cell (lo,l2), cell = lo*3+l2
__constant__ int NPATH[9]  = {1,1,1, 1,3,2, 1,2,3};
__constant__ int PLIST[27] = {0,-1,-1, 1,-1,-1, 2,-1,-1,
                              4,-1,-1, 3,5,7,  6,8,-1,
                              10,-1,-1, 11,13,-1, 9,12,14};

struct W3Params { float w[615]; };  // alpha-scaled wigner3j per path, (i*jd+j)*kd+k
struct QParams  { float q[81];  };  // QCART[k][3][3]

// ==================================================================
// K1: per-node C build.  4 nodes per 256-thread block, grid 1024.
//   t[a][v]  = sum_u feats[off(l1)+u*st+i] * tpw[p][u][v]
//   C[kg][b2]= sum_{p in cell} sum_i w3s_p[i,j,k] * t[toff(p)+i][v]
// ==================================================================
__global__ __launch_bounds__(256) void k1_buildC(const float* __restrict__ feats,
                                                 const float* __restrict__ tpw,
                                                 W3Params w3p)
{
    __shared__ float ws[3840];   // tp_weights [15][16][16]
    __shared__ float xs[4*144];  // feats for 4 nodes
    __shared__ float ts[4*816];  // t[node][a*16+v]
    __shared__ float w3[615];
    const int tid = threadIdx.x;
    const int nb  = blockIdx.x * 4;

    for (int q = tid; q < 3840; q += 256) ws[q] = tpw[q];
    for (int q = tid; q < 576;  q += 256) xs[q] = feats[(size_t)nb*144 + q];
    for (int q = tid; q < 615;  q += 256) w3[q] = w3p.w[q];
    __syncthreads();

    // t-phase: 4*816 outputs
    for (int idx = tid; idx < 4*816; idx += 256) {
        const int nl = idx / 816, rr = idx - nl*816;
        const int a = rr >> 4, v = rr & 15;
        const float* x = xs + nl*144 + A_FB[a];
        const float* w = ws + A_P[a]*256 + v;
        const int st = A_ST[a];
        float acc = 0.f;
        #pragma unroll
        for (int u = 0; u < 16; u++) acc += x[u*st] * w[u*16];
        ts[idx] = acc;
    }
    __syncthreads();

    // fold-phase: 4*1296 outputs
    for (int idx = tid; idx < 4*1296; idx += 256) {
        const int nl = idx / 1296, r2 = idx - nl*1296;
        const int kg = r2 / 144, b2 = r2 - kg*144;
        int lo, k;
        if (kg == 0)      { lo = 0; k = 0; }
        else if (kg < 4)  { lo = 1; k = kg - 1; }
        else              { lo = 2; k = kg - 4; }
        int l2, v, j;
        if (b2 < 16)      { l2 = 0; v = b2; j = 0; }
        else if (b2 < 64) { l2 = 1; int t = b2-16; v = t/3; j = t - v*3; }
        else              { l2 = 2; int t = b2-64; v = t/5; j = t - v*5; }
        const int jd = 2*l2+1, kd = 2*lo+1;
        const int cell = lo*3 + l2;
        float acc = 0.f;
        for (int m = 0; m < NPATH[cell]; m++) {
            const int p = PLIST[cell*3+m];
            const float* wp = w3 + P_W3OFF[p] + j*kd + k;
            const float* tp = ts + nl*816 + P_TOFF[p]*16 + v;
            const int id = P_IDIM[p];
            for (int i = 0; i < id; i++) acc += wp[i*jd*kd] * tp[i*16];
        }
        g_C[(size_t)(nb+nl)*1296 + r2] = acc;
    }
}

// ==================================================================
// K3: pair stage.  Block = (config, row-group-of-16), grid 256, 256 thr.
//   irr[e][k] = sum_b2 C[row][k][b2] * feats[col][b2]
// Thread owns 4 cols {cg, cg+16, cg+32, cg+48} x 9 k.
// ==================================================================
#define XSTRIDE 148
#define SMEM_K3 ((64*XSTRIDE + 16*1296) * 4)

__global__ __launch_bounds__(256) void k3_pairs(const float* __restrict__ feats)
{
    extern __shared__ float sm[];
    float* Xs = sm;                 // [64][XSTRIDE]
    float* Cs = sm + 64*XSTRIDE;    // [16][1296]
    const int tid = threadIdx.x;
    const int cfg = blockIdx.x >> 2;
    const int rg  = blockIdx.x & 3;

    // fill X (col feats for this config; contiguous block of feats)
    {
        const float4* src = (const float4*)(feats + (size_t)cfg*9216);
        for (int idx = tid; idx < 2304; idx += 256) {
            const int col = idx / 36, q = idx - col*36;
            *(float4*)(Xs + col*XSTRIDE + q*4) = src[idx];
        }
    }
    // fill C rows (16 contiguous node rows)
    {
        const float4* src = (const float4*)(g_C + (size_t)(cfg*64 + rg*16)*1296);
        float4* dst = (float4*)Cs;
        for (int idx = tid; idx < 16*324; idx += 256) dst[idx] = src[idx];
    }
    __syncthreads();

    const int r  = tid >> 4;   // row within group (0..15)
    const int cg = tid & 15;   // col base
    const float4* Crow = (const float4*)(Cs + r*1296);

    float acc[4][9];
    #pragma unroll
    for (int c = 0; c < 4; c++)
        #pragma unroll
        for (int k = 0; k < 9; k++) acc[c][k] = 0.f;

    #pragma unroll 2
    for (int q = 0; q < 36; q++) {
        float4 xv[4];
        #pragma unroll
        for (int c = 0; c < 4; c++)
            xv[c] = *(const float4*)(Xs + (cg + c*16)*XSTRIDE + q*4);
        #pragma unroll
        for (int k = 0; k < 9; k++) {
            const float4 cv = Crow[k*36 + q];
            #pragma unroll
            for (int c = 0; c < 4; c++) {
                acc[c][k] += cv.x*xv[c].x + cv.y*xv[c].y
                           + cv.z*xv[c].z + cv.w*xv[c].w;
            }
        }
    }

    const int ebase = cfg*4096 + (rg*16 + r)*64;
    #pragma unroll
    for (int c = 0; c < 4; c++) {
        const size_t e = (size_t)(ebase + cg + c*16);
        #pragma unroll
        for (int k = 0; k < 9; k++) g_irr[e*9 + k] = acc[c][k];
    }
}

// ==================================================================
// K4: cartesian change of basis + symmetrize with partner pair.
// ==================================================================
__global__ __launch_bounds__(512) void k4_cart(float* __restrict__ out, QParams qp)
{
    const int e = blockIdx.x*blockDim.x + threadIdx.x;
    if (e >= NPAIRS) return;
    const int b = e >> 12, i = (e >> 6) & 63, j = e & 63;
    const int ep = (b << 12) | (j << 6) | i;
    float a[9], ap[9];
    #pragma unroll
    for (int k = 0; k < 9; k++) { a[k] = g_irr[(size_t)e*9 + k]; ap[k] = g_irr[(size_t)ep*9 + k]; }
    #pragma unroll
    for (int ii = 0; ii < 3; ii++)
        #pragma unroll
        for (int jj = 0; jj < 3; jj++) {
            float s = 0.f;
            #pragma unroll
            for (int k = 0; k < 9; k++)
                s += a[k]*qp.q[k*9 + ii*3 + jj] + ap[k]*qp.q[k*9 + jj*3 + ii];
            out[(size_t)e*9 + ii*3 + jj] = 0.5f * s;
        }
}

// ==================================================================
// Host: real Wigner-3j (e3nn convention) + QCART, computed per call.
// ==================================================================
static double h_fact(int n){ double r=1; for(int i=2;i<=n;i++) r*=i; return r; }

static double h_su2_cg(int j1,int m1,int j2,int m2,int j3,int m3){
    if (m3 != m1+m2) return 0.0;
    int vmin = std::max(std::max(-j1+j2+m3, -j1+m1), 0);
    int vmax = std::min(std::min(j2+j3+m1, j3-j1+j2), j3+m3);
    double C = sqrt((2.0*j3+1)*h_fact(j3+j1-j2)*h_fact(j3-j1+j2)*h_fact(j1+j2-j3)
               *h_fact(j3+m3)*h_fact(j3-m3)
               /(h_fact(j1+j2+j3+1)*h_fact(j1-m1)*h_fact(j1+m1)*h_fact(j2-m2)*h_fact(j2+m2)));
    double S = 0.0;
    for (int v = vmin; v <= vmax; v++) {
        double term = h_fact(j2+j3+m1-v)*h_fact(j1-m1+v)
                    /(h_fact(v)*h_fact(j3-j1+j2-v)*h_fact(j3+m3-v)*h_fact(v+j1-j2-m3));
        S += (((v+j2+m2) & 1) ? -1.0 : 1.0) * term;
    }
    return C*S;
}

typedef std::complex<double> cd;

static void h_qmat(int l, cd Q[5][5]){
    for (int i = 0; i < 5; i++) for (int j = 0; j < 5; j++) Q[i][j] = cd(0,0);
    const double s = 1.0/sqrt(2.0);
    for (int m = -l; m < 0; m++) {
        Q[l+m][l-m] = cd(s,0);          // l + |m|
        Q[l+m][l+m] = cd(0,-s);         // l - |m|
    }
    Q[l][l] = cd(1,0);
    for (int m = 1; m <= l; m++) {
        double sg = (m & 1) ? -1.0 : 1.0;
        Q[l+m][l+m] = cd(sg*s, 0);
        Q[l+m][l-m] = cd(0, sg*s);
    }
    // multiply by (-i)^l
    cd f = (l==0) ? cd(1,0) : (l==1) ? cd(0,-1) : cd(-1,0);
    for (int i = 0; i < 5; i++) for (int j = 0; j < 5; j++) Q[i][j] *= f;
}

static void h_wigner3j(int l1,int l2,int l3, double W[5][5][5]){
    int d1 = 2*l1+1, d2 = 2*l2+1, d3 = 2*l3+1;
    double C[5][5][5] = {};
    for (int m1 = -l1; m1 <= l1; m1++)
        for (int m2 = -l2; m2 <= l2; m2++) {
            int m3 = m1+m2;
            if (m3 >= -l3 && m3 <= l3)
                C[l1+m1][l2+m2][l3+m3] = h_su2_cg(l1,m1,l2,m2,l3,m3);
        }
    cd Q1[5][5], Q2[5][5], Q3[5][5];
    h_qmat(l1,Q1); h_qmat(l2,Q2); h_qmat(l3,Q3);
    double nrm2 = 0.0;
    for (int j = 0; j < d1; j++)
      for (int lq = 0; lq < d2; lq++)
        for (int n = 0; n < d3; n++) {
            cd acc(0,0);
            for (int i = 0; i < d1; i++)
              for (int k = 0; k < d2; k++)
                for (int m = 0; m < d3; m++) {
                    double c = C[i][k][m];
                    if (c != 0.0) acc += Q1[i][j]*Q2[k][lq]*std::conj(Q3[m][n])*c;
                }
            W[j][lq][n] = acc.real();
            nrm2 += acc.real()*acc.real();
        }
    double inv = 1.0/sqrt(nrm2);
    for (int j = 0; j < d1; j++)
      for (int lq = 0; lq < d2; lq++)
        for (int n = 0; n < d3; n++) W[j][lq][n] *= inv;
}

static void h_build_params(W3Params& wp, QParams& qp){
    static const int PL[15][3] = {{0,0,0},{1,1,0},{2,2,0},{0,1,1},{1,0,1},{1,1,1},
                                  {1,2,1},{2,1,1},{2,2,1},{0,2,2},{2,0,2},{1,1,2},
                                  {1,2,2},{2,1,2},{2,2,2}};
    static const int H_W3OFF[15] = {0,1,10,35,44,53,80,125,170,245,270,295,340,415,490};
    const double alpha[3] = { sqrt(1.0/768.0), sqrt(3.0/1536.0), sqrt(5.0/1536.0) };
    for (int p = 0; p < 15; p++) {
        int l1 = PL[p][0], l2 = PL[p][1], lo = PL[p][2];
        double W[5][5][5];
        h_wigner3j(l1,l2,lo,W);
        int jd = 2*l2+1, kd = 2*lo+1;
        for (int i = 0; i < 2*l1+1; i++)
          for (int j = 0; j < jd; j++)
            for (int k = 0; k < kd; k++)
                wp.w[H_W3OFF[p] + (i*jd+j)*kd + k] = (float)(alpha[lo]*W[i][j][k]);
    }
    // QCART[ko+m][i][j] = sqrt(2l+1) * wigner(1,1,l)[i][j][m]
    int ko = 0;
    for (int l = 0; l <= 2; l++) {
        double W[5][5][5];
        h_wigner3j(1,1,l,W);
        double s = sqrt(2.0*l+1.0);
        for (int m = 0; m < 2*l+1; m++)
          for (int i = 0; i < 3; i++)
            for (int j = 0; j < 3; j++)
                qp.q[(ko+m)*9 + i*3 + j] = (float)(s*W[i][j][m]);
        ko += 2*l+1;
    }
}

// ==================================================================
extern "C" void kernel_launch(void* const* d_in, const int* in_sizes, int n_in,
                              void* d_out, int out_size)
{
    const float* feats = nullptr;
    const float* tpw   = nullptr;
    for (int i = 0; i < n_in; i++) {
        if (in_sizes[i] == NNODES*144)   feats = (const float*)d_in[i];
        else if (in_sizes[i] == 15*256)  tpw   = (const float*)d_in[i];
    }
    W3Params wp; QParams qp;
    h_build_params(wp, qp);

    cudaFuncSetAttribute(k3_pairs, cudaFuncAttributeMaxDynamicSharedMemorySize, SMEM_K3);

    k1_buildC<<<NNODES/4, 256>>>(feats, tpw, wp);
    k3_pairs<<<NCFG*4, 256, SMEM_K3>>>(feats);
    k4_cart<<<NPAIRS/512, 512>>>((float*)d_out, qp);
}

// round 4
// speedup vs baseline: 1.4762x; 1.4762x over previous
#include <cuda_runtime.h>
#include <cuda_bf16.h>
#include <math.h>
#include <complex>
#include <algorithm>

// ---------------- static problem shape ----------------
#define MUL    16
#define NCFG   64
#define NATOM  64
#define NNODES 4096
#define NPAIRS 262144
#define MAXT   320

// ---------------- device scratch (no allocation allowed) ----------------
__device__ float g_C[(size_t)NNODES * 1296];   // C[node][kg(9)][b2(144)]   ~21 MB
__device__ float g_irr[(size_t)NPAIRS * 9];    // irr[pair][9]              ~9.4 MB

struct W3Params { float w[615]; };  // host-side only: alpha-scaled wigner3j
struct QParams  { float q[81];  };  // QCART[k][3][3]
struct FoldParams {                 // sparse fold term table (host-built)
    int   start[82];
    int   r2b[81];
    int   jdv[81];
    int   ta[MAXT];
    float tc[MAXT];
};

// ---------------- f32x2 packed-math helpers ----------------
typedef unsigned long long u64t;
__device__ __forceinline__ u64t pk2(float lo, float hi){
    u64t r; asm("mov.b64 %0, {%1,%2};" : "=l"(r) : "f"(lo), "f"(hi)); return r;
}
__device__ __forceinline__ void fma2(u64t &d, u64t a, u64t b){
    asm("fma.rn.f32x2 %0, %1, %2, %0;" : "+l"(d) : "l"(a), "l"(b));
}
__device__ __forceinline__ void upk2(float &lo, float &hi, u64t v){
    asm("mov.b64 {%0,%1}, %2;" : "=f"(lo), "=f"(hi) : "l"(v));
}
__device__ __forceinline__ float dot4(float4 a, float4 b){
    return a.x*b.x + a.y*b.y + a.z*b.z + a.w*b.w;
}

// ==================================================================
// K1: per-node C build.  128 blocks x 256 threads, 32 nodes/block.
// thread = (nl = tid>>3 in 0..31, v2 = tid&7); handles v = v2 and v2+8.
// Smem (floats): wsT[15*320] | xT[32*148] | ts[32*840]
//   wsT[p*320 + v*20 + u]           (tp_weights transposed, u contiguous)
//   xT [n*148 + blk(l1) + i*16 + u] (feats transposed, u contiguous)
//   ts [n*840 + a*16 + v]           (t-vector, a in 0..50)
// ==================================================================
#define WS_OFF 0
#define XT_OFF (15*320)
#define TS_OFF (15*320 + 32*148)
#define SMEM_K1 ((15*320 + 32*148 + 32*840) * 4)

__global__ __launch_bounds__(256) void k1_buildC(const float* __restrict__ feats,
                                                 const float* __restrict__ tpw,
                                                 FoldParams fp)
{
    extern __shared__ float sm1[];
    float* wsT = sm1 + WS_OFF;
    float* xT  = sm1 + XT_OFF;
    float* ts  = sm1 + TS_OFF;
    const int tid = threadIdx.x;
    const int nbase = blockIdx.x * 32;

    // ---- load + transpose tp_weights: tpw[p*256+u*16+v] -> wsT[p*320+v*20+u]
    for (int idx = tid; idx < 3840; idx += 256) {
        const int p = idx >> 8, r = idx & 255, u = r >> 4, v = r & 15;
        wsT[p*320 + v*20 + u] = tpw[idx];
    }
    // ---- load + transpose feats for 32 nodes
    for (int idx = tid; idx < 32*144; idx += 256) {
        const int n = idx / 144, f = idx - n*144;
        int off;
        if (f < 16)      { off = f; }
        else if (f < 64) { int g = f-16; int u = g/3; off = 16 + (g-3*u)*16 + u; }
        else             { int g = f-64; int u = g/5; off = 64 + (g-5*u)*16 + u; }
        xT[n*148 + off] = feats[(size_t)nbase*144 + idx];
    }
    __syncthreads();

    const int nl = tid >> 3;
    const int v2 = tid & 7;

    // ---- t phase: fully compile-time unrolled over 15 paths
    {
        constexpr int PD1[15]  = {1,3,5,1,3,3,3,5,5,1,5,3,3,5,5};
        constexpr int PFB[15]  = {0,16,64,0,16,16,16,64,64,0,64,16,16,64,64};
        constexpr int PTO[15]  = {0,1,4,9,10,13,16,19,24,29,30,35,38,41,46};
        const float* xbase = xT + nl*148;
        float* tb = ts + nl*840;
        #pragma unroll
        for (int p = 0; p < 15; p++) {
            const float4* wpa = (const float4*)(wsT + p*320 + v2*20);
            const float4* wpb = (const float4*)(wsT + p*320 + (v2+8)*20);
            float4 wa0=wpa[0], wa1=wpa[1], wa2=wpa[2], wa3=wpa[3];
            float4 wb0=wpb[0], wb1=wpb[1], wb2=wpb[2], wb3=wpb[3];
            #pragma unroll
            for (int i = 0; i < PD1[p]; i++) {
                const float4* xr = (const float4*)(xbase + PFB[p] + i*16);
                float4 x0=xr[0], x1=xr[1], x2=xr[2], x3=xr[3];
                float ta = dot4(wa0,x0)+dot4(wa1,x1)+dot4(wa2,x2)+dot4(wa3,x3);
                float tbv = dot4(wb0,x0)+dot4(wb1,x1)+dot4(wb2,x2)+dot4(wb3,x3);
                tb[(PTO[p]+i)*16 + v2]     = ta;
                tb[(PTO[p]+i)*16 + v2 + 8] = tbv;
            }
        }
    }
    __syncthreads();

    // ---- fold phase: sparse table, uniform indices across warp
    {
        const float* tb = ts + nl*840;
        float* cdst = g_C + (size_t)(nbase + nl)*1296;
        for (int c = 0; c < 81; c++) {
            const int s = fp.start[c], e = fp.start[c+1];
            float aa = 0.f, ab = 0.f;
            for (int t = s; t < e; t++) {
                const float cf = fp.tc[t];
                const int   ai = fp.ta[t] * 16;
                aa += cf * tb[ai + v2];
                ab += cf * tb[ai + v2 + 8];
            }
            const int r2 = fp.r2b[c], jd = fp.jdv[c];
            cdst[r2 + v2*jd]     = aa;
            cdst[r2 + (v2+8)*jd] = ab;
        }
    }
}

// ==================================================================
// K3: pair stage with packed f32x2 FMA.
// Block = (cfg, rowgroup of 32): grid 128, 256 threads.
// thread = (r = tid>>3 in 0..31, cg = tid&7); owns cols {cg + c*8}, c=0..7,
// paired as (2cp, 2cp+1) in f32x2 lanes.
// ==================================================================
#define XSTRIDE3 148
#define CSTRIDE  1300
#define SMEM_K3 ((64*XSTRIDE3 + 32*CSTRIDE) * 4)

__global__ __launch_bounds__(256) void k3_pairs(const float* __restrict__ feats)
{
    extern __shared__ float sm[];
    float* Xs = sm;                    // [64][XSTRIDE3]
    float* Cs = sm + 64*XSTRIDE3;      // [32][CSTRIDE]
    const int tid = threadIdx.x;
    const int cfg = blockIdx.x >> 1;
    const int rg  = blockIdx.x & 1;

    // fill X (col feats, contiguous per config)
    {
        const float4* src = (const float4*)(feats + (size_t)cfg*9216);
        for (int idx = tid; idx < 2304; idx += 256) {
            const int col = idx / 36, q = idx - col*36;
            *(float4*)(Xs + col*XSTRIDE3 + q*4) = src[idx];
        }
    }
    // fill C rows (32 rows, padded stride)
    {
        const float4* src = (const float4*)(g_C + (size_t)(cfg*64 + rg*32)*1296);
        for (int idx = tid; idx < 32*324; idx += 256) {
            const int row = idx / 324, q = idx - row*324;
            *(float4*)(Cs + row*CSTRIDE + q*4) = src[idx];
        }
    }
    __syncthreads();

    const int r  = tid >> 3;
    const int cg = tid & 7;
    const float4* Cr4 = (const float4*)(Cs + r*CSTRIDE);

    u64t acc2[4][9];
    #pragma unroll
    for (int cp = 0; cp < 4; cp++)
        #pragma unroll
        for (int k = 0; k < 9; k++) acc2[cp][k] = 0ULL;

    #pragma unroll 2
    for (int q = 0; q < 36; q++) {
        float4 xv[8];
        #pragma unroll
        for (int c = 0; c < 8; c++)
            xv[c] = *(const float4*)(Xs + (cg + c*8)*XSTRIDE3 + q*4);
        u64t xp[4][4];
        #pragma unroll
        for (int cp = 0; cp < 4; cp++) {
            xp[cp][0] = pk2(xv[2*cp].x, xv[2*cp+1].x);
            xp[cp][1] = pk2(xv[2*cp].y, xv[2*cp+1].y);
            xp[cp][2] = pk2(xv[2*cp].z, xv[2*cp+1].z);
            xp[cp][3] = pk2(xv[2*cp].w, xv[2*cp+1].w);
        }
        #pragma unroll
        for (int k = 0; k < 9; k++) {
            const float4 cv = Cr4[k*36 + q];
            u64t cd[4];
            cd[0] = pk2(cv.x, cv.x); cd[1] = pk2(cv.y, cv.y);
            cd[2] = pk2(cv.z, cv.z); cd[3] = pk2(cv.w, cv.w);
            #pragma unroll
            for (int cp = 0; cp < 4; cp++) {
                fma2(acc2[cp][k], cd[0], xp[cp][0]);
                fma2(acc2[cp][k], cd[1], xp[cp][1]);
                fma2(acc2[cp][k], cd[2], xp[cp][2]);
                fma2(acc2[cp][k], cd[3], xp[cp][3]);
            }
        }
    }

    const int ebase = cfg*4096 + (rg*32 + r)*64 + cg;
    #pragma unroll
    for (int cp = 0; cp < 4; cp++) {
        float* o0 = g_irr + (size_t)(ebase + (2*cp)*8)*9;
        float* o1 = g_irr + (size_t)(ebase + (2*cp+1)*8)*9;
        #pragma unroll
        for (int k = 0; k < 9; k++) {
            float lo, hi; upk2(lo, hi, acc2[cp][k]);
            o0[k] = lo; o1[k] = hi;
        }
    }
}

// ==================================================================
// K4: cartesian change of basis + symmetrize with partner pair.
// ==================================================================
__global__ __launch_bounds__(512) void k4_cart(float* __restrict__ out, QParams qp)
{
    const int e = blockIdx.x*blockDim.x + threadIdx.x;
    if (e >= NPAIRS) return;
    const int b = e >> 12, i = (e >> 6) & 63, j = e & 63;
    const int ep = (b << 12) | (j << 6) | i;
    float a[9], ap[9];
    #pragma unroll
    for (int k = 0; k < 9; k++) { a[k] = g_irr[(size_t)e*9 + k]; ap[k] = g_irr[(size_t)ep*9 + k]; }
    #pragma unroll
    for (int ii = 0; ii < 3; ii++)
        #pragma unroll
        for (int jj = 0; jj < 3; jj++) {
            float s = 0.f;
            #pragma unroll
            for (int k = 0; k < 9; k++)
                s += a[k]*qp.q[k*9 + ii*3 + jj] + ap[k]*qp.q[k*9 + jj*3 + ii];
            out[(size_t)e*9 + ii*3 + jj] = 0.5f * s;
        }
}

// ==================================================================
// Host: real Wigner-3j (e3nn convention) + QCART + fold tables, per call.
// ==================================================================
static double h_fact(int n){ double r=1; for(int i=2;i<=n;i++) r*=i; return r; }

static double h_su2_cg(int j1,int m1,int j2,int m2,int j3,int m3){
    if (m3 != m1+m2) return 0.0;
    int vmin = std::max(std::max(-j1+j2+m3, -j1+m1), 0);
    int vmax = std::min(std::min(j2+j3+m1, j3-j1+j2), j3+m3);
    double C = sqrt((2.0*j3+1)*h_fact(j3+j1-j2)*h_fact(j3-j1+j2)*h_fact(j1+j2-j3)
               *h_fact(j3+m3)*h_fact(j3-m3)
               /(h_fact(j1+j2+j3+1)*h_fact(j1-m1)*h_fact(j1+m1)*h_fact(j2-m2)*h_fact(j2+m2)));
    double S = 0.0;
    for (int v = vmin; v <= vmax; v++) {
        double term = h_fact(j2+j3+m1-v)*h_fact(j1-m1+v)
                    /(h_fact(v)*h_fact(j3-j1+j2-v)*h_fact(j3+m3-v)*h_fact(v+j1-j2-m3));
        S += (((v+j2+m2) & 1) ? -1.0 : 1.0) * term;
    }
    return C*S;
}

typedef std::complex<double> cd;

static void h_qmat(int l, cd Q[5][5]){
    for (int i = 0; i < 5; i++) for (int j = 0; j < 5; j++) Q[i][j] = cd(0,0);
    const double s = 1.0/sqrt(2.0);
    for (int m = -l; m < 0; m++) {
        Q[l+m][l-m] = cd(s,0);
        Q[l+m][l+m] = cd(0,-s);
    }
    Q[l][l] = cd(1,0);
    for (int m = 1; m <= l; m++) {
        double sg = (m & 1) ? -1.0 : 1.0;
        Q[l+m][l+m] = cd(sg*s, 0);
        Q[l+m][l-m] = cd(0, sg*s);
    }
    cd f = (l==0) ? cd(1,0) : (l==1) ? cd(0,-1) : cd(-1,0);
    for (int i = 0; i < 5; i++) for (int j = 0; j < 5; j++) Q[i][j] *= f;
}

static void h_wigner3j(int l1,int l2,int l3, double W[5][5][5]){
    int d1 = 2*l1+1, d2 = 2*l2+1, d3 = 2*l3+1;
    double C[5][5][5] = {};
    for (int m1 = -l1; m1 <= l1; m1++)
        for (int m2 = -l2; m2 <= l2; m2++) {
            int m3 = m1+m2;
            if (m3 >= -l3 && m3 <= l3)
                C[l1+m1][l2+m2][l3+m3] = h_su2_cg(l1,m1,l2,m2,l3,m3);
        }
    cd Q1[5][5], Q2[5][5], Q3[5][5];
    h_qmat(l1,Q1); h_qmat(l2,Q2); h_qmat(l3,Q3);
    double nrm2 = 0.0;
    for (int j = 0; j < d1; j++)
      for (int lq = 0; lq < d2; lq++)
        for (int n = 0; n < d3; n++) {
            cd acc(0,0);
            for (int i = 0; i < d1; i++)
              for (int k = 0; k < d2; k++)
                for (int m = 0; m < d3; m++) {
                    double c = C[i][k][m];
                    if (c != 0.0) acc += Q1[i][j]*Q2[k][lq]*std::conj(Q3[m][n])*c;
                }
            W[j][lq][n] = acc.real();
            nrm2 += acc.real()*acc.real();
        }
    double inv = 1.0/sqrt(nrm2);
    for (int j = 0; j < d1; j++)
      for (int lq = 0; lq < d2; lq++)
        for (int n = 0; n < d3; n++) W[j][lq][n] *= inv;
}

static const int H_PL[15][3] = {{0,0,0},{1,1,0},{2,2,0},{0,1,1},{1,0,1},{1,1,1},
                                {1,2,1},{2,1,1},{2,2,1},{0,2,2},{2,0,2},{1,1,2},
                                {1,2,2},{2,1,2},{2,2,2}};
static const int H_W3OFF[15] = {0,1,10,35,44,53,80,125,170,245,270,295,340,415,490};
static const int H_TOFF[15]  = {0,1,4,9,10,13,16,19,24,29,30,35,38,41,46};

static void h_build_params(W3Params& wp, QParams& qp, FoldParams& fp){
    const double alpha[3] = { sqrt(1.0/768.0), sqrt(3.0/1536.0), sqrt(5.0/1536.0) };
    for (int p = 0; p < 15; p++) {
        int l1 = H_PL[p][0], l2 = H_PL[p][1], lo = H_PL[p][2];
        double W[5][5][5];
        h_wigner3j(l1,l2,lo,W);
        int jd = 2*l2+1, kd = 2*lo+1;
        for (int i = 0; i < 2*l1+1; i++)
          for (int j = 0; j < jd; j++)
            for (int k = 0; k < kd; k++)
                wp.w[H_W3OFF[p] + (i*jd+j)*kd + k] = (float)(alpha[lo]*W[i][j][k]);
    }
    // QCART[ko+m][i][j] = sqrt(2l+1) * wigner(1,1,l)[i][j][m]
    int ko = 0;
    for (int l = 0; l <= 2; l++) {
        double W[5][5][5];
        h_wigner3j(1,1,l,W);
        double s = sqrt(2.0*l+1.0);
        for (int m = 0; m < 2*l+1; m++)
          for (int i = 0; i < 3; i++)
            for (int j = 0; j < 3; j++)
                qp.q[(ko+m)*9 + i*3 + j] = (float)(s*W[i][j][m]);
        ko += 2*l+1;
    }
    // fold term tables
    const int l2base[3] = {0,16,64};
    int c = 0, nt = 0;
    for (int kg = 0; kg < 9; kg++) {
        const int lo = (kg==0) ? 0 : (kg<4) ? 1 : 2;
        const int k  = (kg==0) ? 0 : (kg<4) ? (kg-1) : (kg-4);
        for (int l2 = 0; l2 < 3; l2++) {
            const int jd = 2*l2+1;
            for (int j = 0; j < jd; j++) {
                fp.start[c] = nt;
                fp.r2b[c]   = kg*144 + l2base[l2] + j;
                fp.jdv[c]   = jd;
                for (int p = 0; p < 15; p++) {
                    if (H_PL[p][2] != lo || H_PL[p][1] != l2) continue;
                    const int kd = 2*lo+1, id = 2*H_PL[p][0]+1;
                    for (int i = 0; i < id; i++) {
                        float cf = wp.w[H_W3OFF[p] + (i*jd+j)*kd + k];
                        if (fabsf(cf) > 1e-12f && nt < MAXT) {
                            fp.ta[nt] = H_TOFF[p] + i;
                            fp.tc[nt] = cf;
                            nt++;
                        }
                    }
                }
                c++;
            }
        }
    }
    fp.start[81] = nt;
}

// ==================================================================
extern "C" void kernel_launch(void* const* d_in, const int* in_sizes, int n_in,
                              void* d_out, int out_size)
{
    const float* feats = nullptr;
    const float* tpw   = nullptr;
    for (int i = 0; i < n_in; i++) {
        if (in_sizes[i] == NNODES*144)   feats = (const float*)d_in[i];
        else if (in_sizes[i] == 15*256)  tpw   = (const float*)d_in[i];
    }
    W3Params wp; QParams qp; FoldParams fp;
    h_build_params(wp, qp, fp);

    cudaFuncSetAttribute(k1_buildC, cudaFuncAttributeMaxDynamicSharedMemorySize, SMEM_K1);
    cudaFuncSetAttribute(k3_pairs,  cudaFuncAttributeMaxDynamicSharedMemorySize, SMEM_K3);

    k1_buildC<<<NNODES/32, 256, SMEM_K1>>>(feats, tpw, fp);
    k3_pairs<<<NCFG*2, 256, SMEM_K3>>>(feats);
    k4_cart<<<NPAIRS/512, 512>>>((float*)d_out, qp);
}

// round 5
// speedup vs baseline: 1.7284x; 1.1708x over previous
#include <cuda_runtime.h>
#include <cuda_bf16.h>
#include <math.h>
#include <complex>
#include <algorithm>

// ---------------- static problem shape ----------------
#define MUL    16
#define NCFG   64
#define NATOM  64
#define NNODES 4096
#define NPAIRS 262144
#define CROW   2600   // padded floats per node-pair row of g_C

// ---------------- device scratch (no allocation allowed) ----------------
// Row-pair-interleaved C: g_C[np*CROW + (kg*144 + b2)*2 + par],
// np = node>>1, par = node&1.  2048 * 2600 * 4B ~ 21.3 MB
__device__ float g_C[(size_t)2048 * CROW];
__device__ float g_irr[(size_t)NPAIRS * 9];    // irr[pair][9]  ~9.4 MB

struct QParams  { float q[81];  };   // QCART[k][3][3]
struct FoldParams { float cf[756]; };// dense fold coefficients (padded to 4)

// ---------------- f32x2 packed-math helpers ----------------
typedef unsigned long long u64t;
__device__ __forceinline__ u64t pk2(float lo, float hi){
    u64t r; asm("mov.b64 %0, {%1,%2};" : "=l"(r) : "f"(lo), "f"(hi)); return r;
}
__device__ __forceinline__ void fma2(u64t &d, u64t a, u64t b){
    asm("fma.rn.f32x2 %0, %1, %2, %0;" : "+l"(d) : "l"(a), "l"(b));
}
__device__ __forceinline__ void upk2(float &lo, float &hi, u64t v){
    asm("mov.b64 {%0,%1}, %2;" : "=f"(lo), "=f"(hi) : "l"(v));
}
__device__ __forceinline__ float dot4(float4 a, float4 b){
    return a.x*b.x + a.y*b.y + a.z*b.z + a.w*b.w;
}

// ==================================================================
// K1: per-node C build, all register-resident.
// 256 blocks x 256 threads, 16 nodes/block, thread = (nl=tid>>4, v=tid&15).
// t-phase: t[51] in registers. fold: fully unrolled dense table.
// ==================================================================
__global__ __launch_bounds__(256) void k1_buildC(const float* __restrict__ feats,
                                                 const float* __restrict__ tpw,
                                                 FoldParams fp)
{
    __shared__ float wsT[15*320];   // tpw transposed: [p][v*20 + u]
    __shared__ float xT[16*148];    // feats transposed: [n][blk(l1)+i*16+u]
    __shared__ float cfS[756];      // dense fold coefficients
    const int tid = threadIdx.x;
    const int nbase = blockIdx.x * 16;

    for (int idx = tid; idx < 3840; idx += 256) {
        const int p = idx >> 8, r = idx & 255, u = r >> 4, vv = r & 15;
        wsT[p*320 + vv*20 + u] = tpw[idx];
    }
    for (int idx = tid; idx < 16*144; idx += 256) {
        const int n = idx / 144, f = idx - n*144;
        int off;
        if (f < 16)      { off = f; }
        else if (f < 64) { int g = f-16; int u = g/3; off = 16 + (g-3*u)*16 + u; }
        else             { int g = f-64; int u = g/5; off = 64 + (g-5*u)*16 + u; }
        xT[n*148 + off] = feats[(size_t)nbase*144 + idx];
    }
    for (int idx = tid; idx < 756; idx += 256) cfS[idx] = fp.cf[idx];
    __syncthreads();

    const int nl = tid >> 4;
    const int v  = tid & 15;

    // ---- t phase: 51 register-resident t-values ----
    float t[51];
    {
        constexpr int PD1[15] = {1,3,5,1,3,3,3,5,5,1,5,3,3,5,5};
        constexpr int PFB[15] = {0,16,64,0,16,16,16,64,64,0,64,16,16,64,64};
        constexpr int PTO[15] = {0,1,4,9,10,13,16,19,24,29,30,35,38,41,46};
        const float* xbase = xT + nl*148;
        #pragma unroll
        for (int p = 0; p < 15; p++) {
            const float4* wp4 = (const float4*)(wsT + p*320 + v*20);
            const float4 w0 = wp4[0], w1 = wp4[1], w2 = wp4[2], w3v = wp4[3];
            #pragma unroll
            for (int i = 0; i < PD1[p]; i++) {
                const float4* xr = (const float4*)(xbase + PFB[p] + i*16);
                t[PTO[p]+i] = dot4(w0,xr[0]) + dot4(w1,xr[1])
                            + dot4(w2,xr[2]) + dot4(w3v,xr[3]);
            }
        }
    }

    // ---- fold phase: fully unrolled, compile-time indices ----
    {
        constexpr int TL[9][12] = {
          {0,0,0,0,   0,0,0,0,   0,0,0,0},
          {1,2,3,0,   0,0,0,0,   0,0,0,0},
          {4,5,6,7,   8,0,0,0,   0,0,0,0},
          {10,11,12,0, 0,0,0,0,  0,0,0,0},
          {9,13,14,15, 19,20,21,22, 23,0,0,0},
          {16,17,18,24, 25,26,27,28, 0,0,0,0},
          {30,31,32,33, 34,0,0,0,  0,0,0,0},
          {35,36,37,41, 42,43,44,45, 0,0,0,0},
          {29,38,39,40, 46,47,48,49, 50,0,0,0}};
        constexpr int NP4T[9]    = {4,4,8,4,12,8,8,8,12};
        constexpr int KGBASE[9]  = {0,56,136,216,296,388,480,572,664};
        constexpr int L2OFFT[3][3] = {{0,4,16},{0,4,40},{0,8,32}};
        constexpr int L2BASE[3]  = {0,16,64};

        const int node = nbase + nl;
        float* cbase = g_C + (size_t)(node >> 1)*CROW + (node & 1);

        #pragma unroll
        for (int kg = 0; kg < 9; kg++) {
            const int lo = (kg==0) ? 0 : (kg<4) ? 1 : 2;
            #pragma unroll
            for (int l2 = 0; l2 < 3; l2++) {
                const int jd = 2*l2+1;
                const int cell = lo*3 + l2;
                const int np4 = NP4T[cell];
                #pragma unroll
                for (int j = 0; j < jd; j++) {
                    const int cb = KGBASE[kg] + L2OFFT[lo][l2] + j*np4;
                    float acc = 0.f;
                    #pragma unroll
                    for (int g = 0; g < np4/4; g++) {
                        const float4 c4 = *(const float4*)(cfS + cb + g*4);
                        acc += c4.x * t[TL[cell][g*4+0]];
                        acc += c4.y * t[TL[cell][g*4+1]];
                        acc += c4.z * t[TL[cell][g*4+2]];
                        acc += c4.w * t[TL[cell][g*4+3]];
                    }
                    const int b2 = L2BASE[l2] + v*jd + j;
                    cbase[(kg*144 + b2)*2] = acc;
                }
            }
        }
    }
}

// ==================================================================
// K3: pair stage with pre-paired f32x2 C operands.
// Block = (cfg, rowgroup of 32): grid 128, 256 threads.
// thread = (rp = tid>>4 node-pair, cg = tid&15); owns rows {2rp,2rp+1},
// cols {cg + c*16}, c=0..3. acc packed over the row pair.
// ==================================================================
#define XSTRIDE3 148
#define SMEM_K3 ((64*XSTRIDE3 + 16*CROW) * 4)

__global__ __launch_bounds__(256) void k3_pairs(const float* __restrict__ feats)
{
    extern __shared__ float sm[];
    float* Xs = sm;                    // [64][XSTRIDE3]
    float* Cs = sm + 64*XSTRIDE3;      // [16 np][CROW]
    const int tid = threadIdx.x;
    const int cfg = blockIdx.x >> 1;
    const int rg  = blockIdx.x & 1;

    // fill X (col feats, contiguous per config, natural b2 layout)
    {
        const float4* src = (const float4*)(feats + (size_t)cfg*9216);
        for (int idx = tid; idx < 2304; idx += 256) {
            const int col = idx / 36, q = idx - col*36;
            *(float4*)(Xs + col*XSTRIDE3 + q*4) = src[idx];
        }
    }
    // fill C (16 node-pair rows, 2592 used floats each)
    {
        const int npbase = cfg*32 + rg*16;
        for (int idx = tid; idx < 16*648; idx += 256) {
            const int np = idx / 648, q = idx - np*648;
            ((float4*)(Cs + np*CROW))[q] =
                ((const float4*)(g_C + (size_t)(npbase+np)*CROW))[q];
        }
    }
    __syncthreads();

    const int rp = tid >> 4;
    const int cg = tid & 15;
    const float* Crow = Cs + rp*CROW;

    u64t acc[4][9];
    #pragma unroll
    for (int c = 0; c < 4; c++)
        #pragma unroll
        for (int k = 0; k < 9; k++) acc[c][k] = 0ULL;

    #pragma unroll 2
    for (int q = 0; q < 36; q++) {
        float4 xv[4];
        #pragma unroll
        for (int c = 0; c < 4; c++)
            xv[c] = *(const float4*)(Xs + (cg + c*16)*XSTRIDE3 + q*4);
        u64t xp[4][4];
        #pragma unroll
        for (int c = 0; c < 4; c++) {
            xp[c][0] = pk2(xv[c].x, xv[c].x);
            xp[c][1] = pk2(xv[c].y, xv[c].y);
            xp[c][2] = pk2(xv[c].z, xv[c].z);
            xp[c][3] = pk2(xv[c].w, xv[c].w);
        }
        #pragma unroll
        for (int k = 0; k < 9; k++) {
            const u64t* cp = (const u64t*)(Crow + (k*144 + q*4)*2);
            const u64t c0 = cp[0], c1 = cp[1], c2 = cp[2], c3 = cp[3];
            #pragma unroll
            for (int c = 0; c < 4; c++) {
                fma2(acc[c][k], c0, xp[c][0]);
                fma2(acc[c][k], c1, xp[c][1]);
                fma2(acc[c][k], c2, xp[c][2]);
                fma2(acc[c][k], c3, xp[c][3]);
            }
        }
    }

    const int row0 = rg*32 + 2*rp;
    #pragma unroll
    for (int c = 0; c < 4; c++) {
        const size_t e0 = (size_t)cfg*4096 + (size_t)row0*64 + cg + c*16;
        float* o0 = g_irr + e0*9;
        float* o1 = g_irr + (e0 + 64)*9;
        #pragma unroll
        for (int k = 0; k < 9; k++) {
            float lo, hi; upk2(lo, hi, acc[c][k]);
            o0[k] = lo; o1[k] = hi;
        }
    }
}

// ==================================================================
// K4: cartesian change of basis + symmetrize with partner pair.
// ==================================================================
__global__ __launch_bounds__(512) void k4_cart(float* __restrict__ out, QParams qp)
{
    const int e = blockIdx.x*blockDim.x + threadIdx.x;
    if (e >= NPAIRS) return;
    const int b = e >> 12, i = (e >> 6) & 63, j = e & 63;
    const int ep = (b << 12) | (j << 6) | i;
    float a[9], ap[9];
    #pragma unroll
    for (int k = 0; k < 9; k++) { a[k] = g_irr[(size_t)e*9 + k]; ap[k] = g_irr[(size_t)ep*9 + k]; }
    #pragma unroll
    for (int ii = 0; ii < 3; ii++)
        #pragma unroll
        for (int jj = 0; jj < 3; jj++) {
            float s = 0.f;
            #pragma unroll
            for (int k = 0; k < 9; k++)
                s += a[k]*qp.q[k*9 + ii*3 + jj] + ap[k]*qp.q[k*9 + jj*3 + ii];
            out[(size_t)e*9 + ii*3 + jj] = 0.5f * s;
        }
}

// ==================================================================
// Host: real Wigner-3j (e3nn convention) + QCART + fold tables, per call.
// ==================================================================
static double h_fact(int n){ double r=1; for(int i=2;i<=n;i++) r*=i; return r; }

static double h_su2_cg(int j1,int m1,int j2,int m2,int j3,int m3){
    if (m3 != m1+m2) return 0.0;
    int vmin = std::max(std::max(-j1+j2+m3, -j1+m1), 0);
    int vmax = std::min(std::min(j2+j3+m1, j3-j1+j2), j3+m3);
    double C = sqrt((2.0*j3+1)*h_fact(j3+j1-j2)*h_fact(j3-j1+j2)*h_fact(j1+j2-j3)
               *h_fact(j3+m3)*h_fact(j3-m3)
               /(h_fact(j1+j2+j3+1)*h_fact(j1-m1)*h_fact(j1+m1)*h_fact(j2-m2)*h_fact(j2+m2)));
    double S = 0.0;
    for (int v = vmin; v <= vmax; v++) {
        double term = h_fact(j2+j3+m1-v)*h_fact(j1-m1+v)
                    /(h_fact(v)*h_fact(j3-j1+j2-v)*h_fact(j3+m3-v)*h_fact(v+j1-j2-m3));
        S += (((v+j2+m2) & 1) ? -1.0 : 1.0) * term;
    }
    return C*S;
}

typedef std::complex<double> cd;

static void h_qmat(int l, cd Q[5][5]){
    for (int i = 0; i < 5; i++) for (int j = 0; j < 5; j++) Q[i][j] = cd(0,0);
    const double s = 1.0/sqrt(2.0);
    for (int m = -l; m < 0; m++) {
        Q[l+m][l-m] = cd(s,0);
        Q[l+m][l+m] = cd(0,-s);
    }
    Q[l][l] = cd(1,0);
    for (int m = 1; m <= l; m++) {
        double sg = (m & 1) ? -1.0 : 1.0;
        Q[l+m][l+m] = cd(sg*s, 0);
        Q[l+m][l-m] = cd(0, sg*s);
    }
    cd f = (l==0) ? cd(1,0) : (l==1) ? cd(0,-1) : cd(-1,0);
    for (int i = 0; i < 5; i++) for (int j = 0; j < 5; j++) Q[i][j] *= f;
}

static void h_wigner3j(int l1,int l2,int l3, double W[5][5][5]){
    int d1 = 2*l1+1, d2 = 2*l2+1, d3 = 2*l3+1;
    double C[5][5][5] = {};
    for (int m1 = -l1; m1 <= l1; m1++)
        for (int m2 = -l2; m2 <= l2; m2++) {
            int m3 = m1+m2;
            if (m3 >= -l3 && m3 <= l3)
                C[l1+m1][l2+m2][l3+m3] = h_su2_cg(l1,m1,l2,m2,l3,m3);
        }
    cd Q1[5][5], Q2[5][5], Q3[5][5];
    h_qmat(l1,Q1); h_qmat(l2,Q2); h_qmat(l3,Q3);
    double nrm2 = 0.0;
    for (int j = 0; j < d1; j++)
      for (int lq = 0; lq < d2; lq++)
        for (int n = 0; n < d3; n++) {
            cd acc(0,0);
            for (int i = 0; i < d1; i++)
              for (int k = 0; k < d2; k++)
                for (int m = 0; m < d3; m++) {
                    double c = C[i][k][m];
                    if (c != 0.0) acc += Q1[i][j]*Q2[k][lq]*std::conj(Q3[m][n])*c;
                }
            W[j][lq][n] = acc.real();
            nrm2 += acc.real()*acc.real();
        }
    double inv = 1.0/sqrt(nrm2);
    for (int j = 0; j < d1; j++)
      for (int lq = 0; lq < d2; lq++)
        for (int n = 0; n < d3; n++) W[j][lq][n] *= inv;
}

static const int H_PL[15][3] = {{0,0,0},{1,1,0},{2,2,0},{0,1,1},{1,0,1},{1,1,1},
                                {1,2,1},{2,1,1},{2,2,1},{0,2,2},{2,0,2},{1,1,2},
                                {1,2,2},{2,1,2},{2,2,2}};
static const int H_W3OFF[15] = {0,1,10,35,44,53,80,125,170,245,270,295,340,415,490};

static void h_build_params(QParams& qp, FoldParams& fp){
    // alpha-scaled wigner tables
    float w3[615];
    const double alpha[3] = { sqrt(1.0/768.0), sqrt(3.0/1536.0), sqrt(5.0/1536.0) };
    for (int p = 0; p < 15; p++) {
        int l1 = H_PL[p][0], l2 = H_PL[p][1], lo = H_PL[p][2];
        double W[5][5][5];
        h_wigner3j(l1,l2,lo,W);
        int jd = 2*l2+1, kd = 2*lo+1;
        for (int i = 0; i < 2*l1+1; i++)
          for (int j = 0; j < jd; j++)
            for (int k = 0; k < kd; k++)
                w3[H_W3OFF[p] + (i*jd+j)*kd + k] = (float)(alpha[lo]*W[i][j][k]);
    }
    // QCART
    int ko = 0;
    for (int l = 0; l <= 2; l++) {
        double W[5][5][5];
        h_wigner3j(1,1,l,W);
        double s = sqrt(2.0*l+1.0);
        for (int m = 0; m < 2*l+1; m++)
          for (int i = 0; i < 3; i++)
            for (int j = 0; j < 3; j++)
                qp.q[(ko+m)*9 + i*3 + j] = (float)(s*W[i][j][m]);
        ko += 2*l+1;
    }
    // dense fold coefficient table; order must match device-side unroll:
    // kg outer, l2 mid, j inner, slots = (p ascending, i ascending), padded to 4
    int nt = 0;
    for (int kg = 0; kg < 9; kg++) {
        const int lo = (kg==0) ? 0 : (kg<4) ? 1 : 2;
        const int k  = (kg==0) ? 0 : (kg<4) ? (kg-1) : (kg-4);
        const int kd = 2*lo+1;
        for (int l2 = 0; l2 < 3; l2++) {
            const int jd = 2*l2+1;
            // cell term list
            int plist[3], ilist_n = 0, pcount = 0;
            (void)ilist_n;
            int terms_p[12], terms_i[12]; int n = 0;
            for (int p = 0; p < 15; p++) {
                if (H_PL[p][1] != l2 || H_PL[p][2] != lo) continue;
                plist[pcount++] = p;
                for (int i = 0; i < 2*H_PL[p][0]+1; i++) {
                    terms_p[n] = p; terms_i[n] = i; n++;
                }
            }
            (void)plist;
            const int np4 = (n + 3) & ~3;
            for (int j = 0; j < jd; j++)
                for (int s = 0; s < np4; s++)
                    fp.cf[nt++] = (s < n)
                        ? w3[H_W3OFF[terms_p[s]] + (terms_i[s]*jd + j)*kd + k]
                        : 0.0f;
        }
    }
    // nt must be 756
}

// ==================================================================
extern "C" void kernel_launch(void* const* d_in, const int* in_sizes, int n_in,
                              void* d_out, int out_size)
{
    const float* feats = nullptr;
    const float* tpw   = nullptr;
    for (int i = 0; i < n_in; i++) {
        if (in_sizes[i] == NNODES*144)   feats = (const float*)d_in[i];
        else if (in_sizes[i] == 15*256)  tpw   = (const float*)d_in[i];
    }
    QParams qp; FoldParams fp;
    h_build_params(qp, fp);

    cudaFuncSetAttribute(k3_pairs, cudaFuncAttributeMaxDynamicSharedMemorySize, SMEM_K3);

    k1_buildC<<<NNODES/16, 256>>>(feats, tpw, fp);
    k3_pairs<<<NCFG*2, 256, SMEM_K3>>>(feats);
    k4_cart<<<NPAIRS/512, 512>>>((float*)d_out, qp);
}

// round 6
// speedup vs baseline: 2.4436x; 1.4138x over previous
#include <cuda_runtime.h>
#include <cuda_bf16.h>
#include <math.h>
#include <complex>
#include <algorithm>

// ---------------- static problem shape ----------------
#define MUL    16
#define NCFG   64
#define NATOM  64
#define NNODES 4096
#define NPAIRS 262144
#define CROW   2600   // padded floats per node-pair row of g_C

// ---------------- device scratch (no allocation allowed) ----------------
// Row-pair-interleaved C: g_C[np*CROW + (kg*144 + b2)*2 + par]
__device__ float g_C[(size_t)2048 * CROW];
// planar irr: g_irr[k*NPAIRS + e]
__device__ float g_irr[(size_t)9 * NPAIRS];

struct QParams  { float q[81];  };   // QCART[k][3][3]
struct FoldParams { float cf[756]; };// dense fold coefficients (padded to 4)

// ---------------- f32x2 packed-math helpers ----------------
typedef unsigned long long u64t;
__device__ __forceinline__ u64t pk2(float lo, float hi){
    u64t r; asm("mov.b64 %0, {%1,%2};" : "=l"(r) : "f"(lo), "f"(hi)); return r;
}
__device__ __forceinline__ void fma2(u64t &d, u64t a, u64t b){
    asm("fma.rn.f32x2 %0, %1, %2, %0;" : "+l"(d) : "l"(a), "l"(b));
}
__device__ __forceinline__ void upk2(float &lo, float &hi, u64t v){
    asm("mov.b64 {%0,%1}, %2;" : "=f"(lo), "=f"(hi) : "l"(v));
}
__device__ __forceinline__ float dot4(float4 a, float4 b){
    return a.x*b.x + a.y*b.y + a.z*b.z + a.w*b.w;
}

// ==================================================================
// K1: per-node C build, register t + smem-staged coalesced C stores.
// 256 blocks x 256 threads, 16 nodes/block, thread = (nl=tid>>4, v=tid&15).
// smem: [cfS 768][ union: (wsT 4800 | xT 2368)  /  stage 20736 ]
// ==================================================================
#define K1_CF    0
#define K1_WS    768
#define K1_XT    (768 + 4800)
#define K1_STAGE 768
#define SMEM_K1  ((768 + 20736) * 4)   // 86016 B

__global__ __launch_bounds__(256, 2) void k1_buildC(const float* __restrict__ feats,
                                                    const float* __restrict__ tpw,
                                                    FoldParams fp)
{
    extern __shared__ float sm1[];
    float* cfS = sm1 + K1_CF;
    float* wsT = sm1 + K1_WS;
    float* xT  = sm1 + K1_XT;
    float* stage = sm1 + K1_STAGE;
    const int tid = threadIdx.x;
    const int nbase = blockIdx.x * 16;

    for (int idx = tid; idx < 3840; idx += 256) {
        const int p = idx >> 8, r = idx & 255, u = r >> 4, vv = r & 15;
        wsT[p*320 + vv*20 + u] = tpw[idx];
    }
    for (int idx = tid; idx < 16*144; idx += 256) {
        const int n = idx / 144, f = idx - n*144;
        int off;
        if (f < 16)      { off = f; }
        else if (f < 64) { int g = f-16; int u = g/3; off = 16 + (g-3*u)*16 + u; }
        else             { int g = f-64; int u = g/5; off = 64 + (g-5*u)*16 + u; }
        xT[n*148 + off] = feats[(size_t)nbase*144 + idx];
    }
    for (int idx = tid; idx < 756; idx += 256) cfS[idx] = fp.cf[idx];
    __syncthreads();

    const int nl = tid >> 4;
    const int v  = tid & 15;

    // ---- t phase: 51 register-resident t-values ----
    float t[51];
    {
        constexpr int PD1[15] = {1,3,5,1,3,3,3,5,5,1,5,3,3,5,5};
        constexpr int PFB[15] = {0,16,64,0,16,16,16,64,64,0,64,16,16,64,64};
        constexpr int PTO[15] = {0,1,4,9,10,13,16,19,24,29,30,35,38,41,46};
        const float* xbase = xT + nl*148;
        #pragma unroll
        for (int p = 0; p < 15; p++) {
            const float4* wp4 = (const float4*)(wsT + p*320 + v*20);
            const float4 w0 = wp4[0], w1 = wp4[1], w2 = wp4[2], w3v = wp4[3];
            #pragma unroll
            for (int i = 0; i < PD1[p]; i++) {
                const float4* xr = (const float4*)(xbase + PFB[p] + i*16);
                t[PTO[p]+i] = dot4(w0,xr[0]) + dot4(w1,xr[1])
                            + dot4(w2,xr[2]) + dot4(w3v,xr[3]);
            }
        }
    }
    __syncthreads();   // wsT/xT dead; stage overlays them

    // ---- fold phase: fully unrolled, write into smem stage ----
    {
        constexpr int TL[9][12] = {
          {0,0,0,0,   0,0,0,0,   0,0,0,0},
          {1,2,3,0,   0,0,0,0,   0,0,0,0},
          {4,5,6,7,   8,0,0,0,   0,0,0,0},
          {10,11,12,0, 0,0,0,0,  0,0,0,0},
          {9,13,14,15, 19,20,21,22, 23,0,0,0},
          {16,17,18,24, 25,26,27,28, 0,0,0,0},
          {30,31,32,33, 34,0,0,0,  0,0,0,0},
          {35,36,37,41, 42,43,44,45, 0,0,0,0},
          {29,38,39,40, 46,47,48,49, 50,0,0,0}};
        constexpr int NP4T[9]    = {4,4,8,4,12,8,8,8,12};
        constexpr int KGBASE[9]  = {0,56,136,216,296,388,480,572,664};
        constexpr int L2OFFT[3][3] = {{0,4,16},{0,4,40},{0,8,32}};
        constexpr int L2BASE[3]  = {0,16,64};

        float* cst = stage + (nl >> 1)*2592 + (nl & 1);

        #pragma unroll
        for (int kg = 0; kg < 9; kg++) {
            const int lo = (kg==0) ? 0 : (kg<4) ? 1 : 2;
            #pragma unroll
            for (int l2 = 0; l2 < 3; l2++) {
                const int jd = 2*l2+1;
                const int cell = lo*3 + l2;
                const int np4 = NP4T[cell];
                #pragma unroll
                for (int j = 0; j < jd; j++) {
                    const int cb = KGBASE[kg] + L2OFFT[lo][l2] + j*np4;
                    float acc = 0.f;
                    #pragma unroll
                    for (int g = 0; g < np4/4; g++) {
                        const float4 c4 = *(const float4*)(cfS + cb + g*4);
                        acc += c4.x * t[TL[cell][g*4+0]];
                        acc += c4.y * t[TL[cell][g*4+1]];
                        acc += c4.z * t[TL[cell][g*4+2]];
                        acc += c4.w * t[TL[cell][g*4+3]];
                    }
                    const int b2 = L2BASE[l2] + v*jd + j;
                    cst[(kg*144 + b2)*2] = acc;
                }
            }
        }
    }
    __syncthreads();

    // ---- coalesced copy stage -> g_C ----
    {
        const int npbase = blockIdx.x * 8;
        for (int idx = tid; idx < 8*648; idx += 256) {
            const int np = idx / 648, q = idx - np*648;
            ((float4*)(g_C + (size_t)(npbase+np)*CROW))[q] =
                ((const float4*)(stage + np*2592))[q];
        }
    }
}

// ==================================================================
// K3: pair stage, 512 threads, warp-uniform C row (broadcast LDS).
// Block = (cfg, rowhalf of 32): grid 128.
// thread = (rp = tid>>5 node-pair, cg = tid&31); cols {cg, cg+32}.
// ==================================================================
#define XSTRIDE3 148
#define SMEM_K3 ((64*XSTRIDE3 + 16*CROW) * 4)

__global__ __launch_bounds__(512) void k3_pairs(const float* __restrict__ feats)
{
    extern __shared__ float sm[];
    float* Xs = sm;                      // [64][148]
    float* Cs = sm + 64*XSTRIDE3;        // [16 np][2600]
    const int tid = threadIdx.x;
    const int cfg = blockIdx.x >> 1;
    const int rg  = blockIdx.x & 1;

    {
        const float4* src = (const float4*)(feats + (size_t)cfg*9216);
        for (int idx = tid; idx < 2304; idx += 512) {
            const int col = idx / 36, q = idx - col*36;
            *(float4*)(Xs + col*XSTRIDE3 + q*4) = src[idx];
        }
    }
    {
        const int npbase = cfg*32 + rg*16;
        for (int idx = tid; idx < 16*648; idx += 512) {
            const int np = idx / 648, q = idx - np*648;
            ((float4*)(Cs + np*CROW))[q] =
                ((const float4*)(g_C + (size_t)(npbase+np)*CROW))[q];
        }
    }
    __syncthreads();

    const int rp = tid >> 5;
    const int cg = tid & 31;
    const float* Crow = Cs + rp*CROW;

    u64t acc[2][9];
    #pragma unroll
    for (int c = 0; c < 2; c++)
        #pragma unroll
        for (int k = 0; k < 9; k++) acc[c][k] = 0ULL;

    #pragma unroll 2
    for (int q = 0; q < 36; q++) {
        const float4 xv0 = *(const float4*)(Xs + cg*XSTRIDE3 + q*4);
        const float4 xv1 = *(const float4*)(Xs + (cg+32)*XSTRIDE3 + q*4);
        u64t xp0[4], xp1[4];
        xp0[0] = pk2(xv0.x, xv0.x); xp0[1] = pk2(xv0.y, xv0.y);
        xp0[2] = pk2(xv0.z, xv0.z); xp0[3] = pk2(xv0.w, xv0.w);
        xp1[0] = pk2(xv1.x, xv1.x); xp1[1] = pk2(xv1.y, xv1.y);
        xp1[2] = pk2(xv1.z, xv1.z); xp1[3] = pk2(xv1.w, xv1.w);
        #pragma unroll
        for (int k = 0; k < 9; k++) {
            const double2* cp = (const double2*)(Crow + (k*144 + q*4)*2);
            const double2 d0 = cp[0], d1 = cp[1];
            const u64t c0 = __double_as_longlong(d0.x);
            const u64t c1 = __double_as_longlong(d0.y);
            const u64t c2 = __double_as_longlong(d1.x);
            const u64t c3 = __double_as_longlong(d1.y);
            fma2(acc[0][k], c0, xp0[0]); fma2(acc[0][k], c1, xp0[1]);
            fma2(acc[0][k], c2, xp0[2]); fma2(acc[0][k], c3, xp0[3]);
            fma2(acc[1][k], c0, xp1[0]); fma2(acc[1][k], c1, xp1[1]);
            fma2(acc[1][k], c2, xp1[2]); fma2(acc[1][k], c3, xp1[3]);
        }
    }

    const int row0 = rg*32 + 2*rp;
    const int e0 = cfg*4096 + row0*64 + cg;
    #pragma unroll
    for (int c = 0; c < 2; c++) {
        const int ec = e0 + c*32;
        #pragma unroll
        for (int k = 0; k < 9; k++) {
            float lo, hi; upk2(lo, hi, acc[c][k]);
            g_irr[(size_t)k*NPAIRS + ec]      = lo;
            g_irr[(size_t)k*NPAIRS + ec + 64] = hi;
        }
    }
}

// ==================================================================
// K4: cartesian change of basis + symmetrize; smem transpose tiles.
// Block = (cfg, 2x2 quadrant of 32x32 pairs): grid 256, 256 threads.
// smem: A[9*1024] | B[9*1056 pad33] | obuf[2304]
// ==================================================================
#define K4_A    0
#define K4_B    9216
#define K4_O    (9216 + 9504)
#define SMEM_K4 ((9216 + 9504 + 2304) * 4)  // 84096 B

__global__ __launch_bounds__(256) void k4_cart(float* __restrict__ out, QParams qp)
{
    extern __shared__ float sm4[];
    float* A = sm4 + K4_A;
    float* B = sm4 + K4_B;
    float* obuf = sm4 + K4_O;
    const int tid = threadIdx.x;
    const int cfg = blockIdx.x >> 2;
    const int ib  = (blockIdx.x >> 1) & 1;
    const int jb  = blockIdx.x & 1;
    const int ebase = cfg*4096;

    for (int idx = tid; idx < 9216; idx += 256) {
        const int k = idx >> 10, p = idx & 1023, r = p >> 5, c = p & 31;
        A[idx] = g_irr[(size_t)k*NPAIRS + ebase + (ib*32+r)*64 + jb*32 + c];
        B[k*1056 + r*33 + c] =
            g_irr[(size_t)k*NPAIRS + ebase + (jb*32+r)*64 + ib*32 + c];
    }
    __syncthreads();

    for (int s = 0; s < 4; s++) {
        const int p = s*256 + tid;
        const int r = p >> 5, c = p & 31;
        float a[9], ap[9];
        #pragma unroll
        for (int k = 0; k < 9; k++) {
            a[k]  = A[k*1024 + p];
            ap[k] = B[k*1056 + c*33 + r];
        }
        #pragma unroll
        for (int ii = 0; ii < 3; ii++)
            #pragma unroll
            for (int jj = 0; jj < 3; jj++) {
                float sacc = 0.f;
                #pragma unroll
                for (int k = 0; k < 9; k++)
                    sacc += a[k]*qp.q[k*9 + ii*3 + jj] + ap[k]*qp.q[k*9 + jj*3 + ii];
                obuf[tid*9 + ii*3 + jj] = 0.5f * sacc;
            }
        __syncthreads();
        // coalesced copy of this 8-row chunk (rows s*8..s*8+7 of the tile)
        for (int idx = tid; idx < 576; idx += 256) {
            const int rl = idx / 72, q = idx - rl*72;
            ((float4*)(out + (size_t)(ebase + (ib*32 + s*8 + rl)*64 + jb*32)*9))[q] =
                ((const float4*)(obuf + rl*288))[q];
        }
        __syncthreads();
    }
}

// ==================================================================
// Host: real Wigner-3j (e3nn convention) + QCART + fold tables, per call.
// ==================================================================
static double h_fact(int n){ double r=1; for(int i=2;i<=n;i++) r*=i; return r; }

static double h_su2_cg(int j1,int m1,int j2,int m2,int j3,int m3){
    if (m3 != m1+m2) return 0.0;
    int vmin = std::max(std::max(-j1+j2+m3, -j1+m1), 0);
    int vmax = std::min(std::min(j2+j3+m1, j3-j1+j2), j3+m3);
    double C = sqrt((2.0*j3+1)*h_fact(j3+j1-j2)*h_fact(j3-j1+j2)*h_fact(j1+j2-j3)
               *h_fact(j3+m3)*h_fact(j3-m3)
               /(h_fact(j1+j2+j3+1)*h_fact(j1-m1)*h_fact(j1+m1)*h_fact(j2-m2)*h_fact(j2+m2)));
    double S = 0.0;
    for (int v = vmin; v <= vmax; v++) {
        double term = h_fact(j2+j3+m1-v)*h_fact(j1-m1+v)
                    /(h_fact(v)*h_fact(j3-j1+j2-v)*h_fact(j3+m3-v)*h_fact(v+j1-j2-m3));
        S += (((v+j2+m2) & 1) ? -1.0 : 1.0) * term;
    }
    return C*S;
}

typedef std::complex<double> cd;

static void h_qmat(int l, cd Q[5][5]){
    for (int i = 0; i < 5; i++) for (int j = 0; j < 5; j++) Q[i][j] = cd(0,0);
    const double s = 1.0/sqrt(2.0);
    for (int m = -l; m < 0; m++) {
        Q[l+m][l-m] = cd(s,0);
        Q[l+m][l+m] = cd(0,-s);
    }
    Q[l][l] = cd(1,0);
    for (int m = 1; m <= l; m++) {
        double sg = (m & 1) ? -1.0 : 1.0;
        Q[l+m][l+m] = cd(sg*s, 0);
        Q[l+m][l-m] = cd(0, sg*s);
    }
    cd f = (l==0) ? cd(1,0) : (l==1) ? cd(0,-1) : cd(-1,0);
    for (int i = 0; i < 5; i++) for (int j = 0; j < 5; j++) Q[i][j] *= f;
}

static void h_wigner3j(int l1,int l2,int l3, double W[5][5][5]){
    int d1 = 2*l1+1, d2 = 2*l2+1, d3 = 2*l3+1;
    double C[5][5][5] = {};
    for (int m1 = -l1; m1 <= l1; m1++)
        for (int m2 = -l2; m2 <= l2; m2++) {
            int m3 = m1+m2;
            if (m3 >= -l3 && m3 <= l3)
                C[l1+m1][l2+m2][l3+m3] = h_su2_cg(l1,m1,l2,m2,l3,m3);
        }
    cd Q1[5][5], Q2[5][5], Q3[5][5];
    h_qmat(l1,Q1); h_qmat(l2,Q2); h_qmat(l3,Q3);
    double nrm2 = 0.0;
    for (int j = 0; j < d1; j++)
      for (int lq = 0; lq < d2; lq++)
        for (int n = 0; n < d3; n++) {
            cd acc(0,0);
            for (int i = 0; i < d1; i++)
              for (int k = 0; k < d2; k++)
                for (int m = 0; m < d3; m++) {
                    double c = C[i][k][m];
                    if (c != 0.0) acc += Q1[i][j]*Q2[k][lq]*std::conj(Q3[m][n])*c;
                }
            W[j][lq][n] = acc.real();
            nrm2 += acc.real()*acc.real();
        }
    double inv = 1.0/sqrt(nrm2);
    for (int j = 0; j < d1; j++)
      for (int lq = 0; lq < d2; lq++)
        for (int n = 0; n < d3; n++) W[j][lq][n] *= inv;
}

static const int H_PL[15][3] = {{0,0,0},{1,1,0},{2,2,0},{0,1,1},{1,0,1},{1,1,1},
                                {1,2,1},{2,1,1},{2,2,1},{0,2,2},{2,0,2},{1,1,2},
                                {1,2,2},{2,1,2},{2,2,2}};
static const int H_W3OFF[15] = {0,1,10,35,44,53,80,125,170,245,270,295,340,415,490};

static void h_build_params(QParams& qp, FoldParams& fp){
    float w3[615];
    const double alpha[3] = { sqrt(1.0/768.0), sqrt(3.0/1536.0), sqrt(5.0/1536.0) };
    for (int p = 0; p < 15; p++) {
        int l1 = H_PL[p][0], l2 = H_PL[p][1], lo = H_PL[p][2];
        double W[5][5][5];
        h_wigner3j(l1,l2,lo,W);
        int jd = 2*l2+1, kd = 2*lo+1;
        for (int i = 0; i < 2*l1+1; i++)
          for (int j = 0; j < jd; j++)
            for (int k = 0; k < kd; k++)
                w3[H_W3OFF[p] + (i*jd+j)*kd + k] = (float)(alpha[lo]*W[i][j][k]);
    }
    int ko = 0;
    for (int l = 0; l <= 2; l++) {
        double W[5][5][5];
        h_wigner3j(1,1,l,W);
        double s = sqrt(2.0*l+1.0);
        for (int m = 0; m < 2*l+1; m++)
          for (int i = 0; i < 3; i++)
            for (int j = 0; j < 3; j++)
                qp.q[(ko+m)*9 + i*3 + j] = (float)(s*W[i][j][m]);
        ko += 2*l+1;
    }
    int nt = 0;
    for (int kg = 0; kg < 9; kg++) {
        const int lo = (kg==0) ? 0 : (kg<4) ? 1 : 2;
        const int k  = (kg==0) ? 0 : (kg<4) ? (kg-1) : (kg-4);
        const int kd = 2*lo+1;
        for (int l2 = 0; l2 < 3; l2++) {
            const int jd = 2*l2+1;
            int terms_p[12], terms_i[12]; int n = 0;
            for (int p = 0; p < 15; p++) {
                if (H_PL[p][1] != l2 || H_PL[p][2] != lo) continue;
                for (int i = 0; i < 2*H_PL[p][0]+1; i++) {
                    terms_p[n] = p; terms_i[n] = i; n++;
                }
            }
            const int np4 = (n + 3) & ~3;
            for (int j = 0; j < jd; j++)
                for (int s = 0; s < np4; s++)
                    fp.cf[nt++] = (s < n)
                        ? w3[H_W3OFF[terms_p[s]] + (terms_i[s]*jd + j)*kd + k]
                        : 0.0f;
        }
    }
}

// ==================================================================
extern "C" void kernel_launch(void* const* d_in, const int* in_sizes, int n_in,
                              void* d_out, int out_size)
{
    const float* feats = nullptr;
    const float* tpw   = nullptr;
    for (int i = 0; i < n_in; i++) {
        if (in_sizes[i] == NNODES*144)   feats = (const float*)d_in[i];
        else if (in_sizes[i] == 15*256)  tpw   = (const float*)d_in[i];
    }
    QParams qp; FoldParams fp;
    h_build_params(qp, fp);

    cudaFuncSetAttribute(k1_buildC, cudaFuncAttributeMaxDynamicSharedMemorySize, SMEM_K1);
    cudaFuncSetAttribute(k3_pairs,  cudaFuncAttributeMaxDynamicSharedMemorySize, SMEM_K3);
    cudaFuncSetAttribute(k4_cart,   cudaFuncAttributeMaxDynamicSharedMemorySize, SMEM_K4);

    k1_buildC<<<NNODES/16, 256, SMEM_K1>>>(feats, tpw, fp);
    k3_pairs<<<NCFG*2, 512, SMEM_K3>>>(feats);
    k4_cart<<<NCFG*4, 256, SMEM_K4>>>((float*)d_out, qp);
}

// round 10
// speedup vs baseline: 2.5375x; 1.0384x over previous
#include <cuda_runtime.h>
#include <cuda_bf16.h>
#include <math.h>
#include <complex>
#include <algorithm>

// ---------------- static problem shape ----------------
#define MUL    16
#define NCFG   64
#define NATOM  64
#define NNODES 4096
#define NPAIRS 262144
#define CROW   2600   // padded floats per node-pair row of g_C

// ---------------- device scratch (no allocation allowed) ----------------
// Row-pair-interleaved C: g_C[np*CROW + (kg*144 + b2)*2 + par]
__device__ float g_C[(size_t)2048 * CROW];
// planar irr: g_irr[k*NPAIRS + e]
__device__ float g_irr[(size_t)9 * NPAIRS];

struct QParams  { float q[81];  };   // QCART[k][3][3]
struct FoldParams { float cf[724]; };// cell-ordered fold coefficients (slices padded to 4)

// ---------------- f32x2 packed-math helpers ----------------
typedef unsigned long long u64t;
__device__ __forceinline__ u64t pk2(float lo, float hi){
    u64t r; asm("mov.b64 %0, {%1,%2};" : "=l"(r) : "f"(lo), "f"(hi)); return r;
}
__device__ __forceinline__ void fma2(u64t &d, u64t a, u64t b){
    asm("fma.rn.f32x2 %0, %1, %2, %0;" : "+l"(d) : "l"(a), "l"(b));
}
__device__ __forceinline__ void upk2(float &lo, float &hi, u64t v){
    asm("mov.b64 {%0,%1}, %2;" : "=f"(lo), "=f"(hi) : "l"(v));
}
__device__ __forceinline__ float dot4(float4 a, float4 b){
    return a.x*b.x + a.y*b.y + a.z*b.z + a.w*b.w;
}

// ==================================================================
// K1: per-node C build, cell-streamed (no big live state, no spills).
// 512 blocks x 128 threads, 8 nodes/block, thread = (nl=tid>>4, v=tid&15).
// smem: [cf 724][wsT 4800][xT 1184][stage 5760]  = 49872 B
// Two-phase staging: kg 0-3 (lo<=1) then kg 4-8 (lo=2).
// ==================================================================
#define K1_CF    0
#define K1_WS    724
#define K1_XT    (724 + 4800)
#define K1_STAGE (724 + 4800 + 1184)
#define SMEM_K1  ((724 + 4800 + 1184 + 5760) * 4)

// one (lo,l2) cell: accumulate out[jd*kd], then write to stage chunk.
// cst points at this thread's (np, par) base within the current chunk.
template<int L2, int LO, int NP, int P0, int P1, int P2, int CFB, int CKG0>
__device__ __forceinline__ void do_cell(const float* __restrict__ xb,
                                        const float* __restrict__ wsT,
                                        const float* __restrict__ cfS,
                                        float* __restrict__ cst,
                                        const int v)
{
    constexpr int jd = 2*L2+1, kd = 2*LO+1;
    constexpr int S  = (jd*kd + 3) & ~3;
    constexpr int PLL[3] = {P0, P1, P2};
    constexpr int PD [15] = {1,3,5,1,3,3,3,5,5,1,5,3,3,5,5};
    constexpr int PFB[15] = {0,16,64,0,16,16,16,64,64,0,64,16,16,64,64};
    constexpr int L2B[3] = {0,16,64};

    float out[jd*kd];
    #pragma unroll
    for (int q = 0; q < jd*kd; q++) out[q] = 0.f;

    int slice = 0;
    #pragma unroll
    for (int pp = 0; pp < NP; pp++) {
        const int p = PLL[pp];
        const float4* w4 = (const float4*)(wsT + p*320 + v*20);
        const float4 w0 = w4[0], w1 = w4[1], w2 = w4[2], w3v = w4[3];
        #pragma unroll
        for (int i = 0; i < PD[PLL[pp]]; i++) {
            const float4* xr = (const float4*)(xb + PFB[PLL[pp]] + i*16);
            const float t = dot4(w0,xr[0]) + dot4(w1,xr[1])
                          + dot4(w2,xr[2]) + dot4(w3v,xr[3]);
            const int co = CFB + slice*S;
            #pragma unroll
            for (int g = 0; g < S/4; g++) {
                const float4 c4 = *(const float4*)(cfS + co + g*4);
                const float cc[4] = {c4.x, c4.y, c4.z, c4.w};
                #pragma unroll
                for (int l = 0; l < 4; l++) {
                    constexpr int JK = jd*kd;
                    const int lin = g*4 + l;
                    if (lin < JK) out[lin] += cc[l]*t;
                }
            }
            slice++;
        }
    }
    #pragma unroll
    for (int j = 0; j < jd; j++)
        #pragma unroll
        for (int k = 0; k < kd; k++)
            cst[((CKG0 + k)*144 + L2B[L2] + v*jd + j)*2] = out[j*kd + k];
}

__global__ __launch_bounds__(128, 4) void k1_buildC(const float* __restrict__ feats,
                                                    const float* __restrict__ tpw,
                                                    FoldParams fp)
{
    extern __shared__ float sm1[];
    float* cfS   = sm1 + K1_CF;
    float* wsT   = sm1 + K1_WS;
    float* xT    = sm1 + K1_XT;
    float* stage = sm1 + K1_STAGE;
    const int tid = threadIdx.x;
    const int nbase = blockIdx.x * 8;

    for (int idx = tid; idx < 3840; idx += 128) {
        const int p = idx >> 8, r = idx & 255, u = r >> 4, vv = r & 15;
        wsT[p*320 + vv*20 + u] = tpw[idx];
    }
    for (int idx = tid; idx < 8*144; idx += 128) {
        const int n = idx / 144, f = idx - n*144;
        int off;
        if (f < 16)      { off = f; }
        else if (f < 64) { int g = f-16; int u = g/3; off = 16 + (g-3*u)*16 + u; }
        else             { int g = f-64; int u = g/5; off = 64 + (g-5*u)*16 + u; }
        xT[n*148 + off] = feats[(size_t)nbase*144 + idx];
    }
    for (int idx = tid; idx < 724; idx += 128) cfS[idx] = fp.cf[idx];
    __syncthreads();

    const int nl = tid >> 4;
    const int v  = tid & 15;
    const float* xb = xT + nl*148;
    const int npl = nl >> 1, par = nl & 1;
    const int npbase = blockIdx.x * 4;

    // ---- phase A: lo 0,1 cells -> stage chunk (4 kg * 288) ----
    {
        float* cstA = stage + npl*1152 + par;
        do_cell<0,0,1, 0,0,0,   0, 0>(xb, wsT, cfS, cstA, v);
        do_cell<1,0,1, 1,0,0,   4, 0>(xb, wsT, cfS, cstA, v);
        do_cell<2,0,1, 2,0,0,  16, 0>(xb, wsT, cfS, cstA, v);
        do_cell<0,1,1, 4,0,0,  56, 1>(xb, wsT, cfS, cstA, v);
        do_cell<1,1,3, 3,5,7,  68, 1>(xb, wsT, cfS, cstA, v);
        do_cell<2,1,2, 6,8,0, 176, 1>(xb, wsT, cfS, cstA, v);
    }
    __syncthreads();
    for (int idx = tid; idx < 4*288; idx += 128) {
        const int np = idx / 288, q = idx - np*288;
        ((float4*)(g_C + (size_t)(npbase+np)*CROW))[q] =
            ((const float4*)(stage + np*1152))[q];
    }
    __syncthreads();

    // ---- phase B: lo 2 cells -> stage chunk (5 kg * 288) ----
    {
        float* cstB = stage + npl*1440 + par;
        do_cell<0,2,1, 10, 0, 0, 304, 0>(xb, wsT, cfS, cstB, v);
        do_cell<1,2,2, 11,13, 0, 344, 0>(xb, wsT, cfS, cstB, v);
        do_cell<2,2,3, 9,12,14, 472, 0>(xb, wsT, cfS, cstB, v);
    }
    __syncthreads();
    for (int idx = tid; idx < 4*360; idx += 128) {
        const int np = idx / 360, q = idx - np*360;
        ((float4*)(g_C + (size_t)(npbase+np)*CROW + 1152))[q] =
            ((const float4*)(stage + np*1440))[q];
    }
}

// ==================================================================
// K3: pair stage, 512 threads, warp-uniform C row (broadcast LDS).
// Block = (cfg, rowhalf of 32): grid 128.
// thread = (rp = tid>>5 node-pair, cg = tid&31); cols {cg, cg+32}.
// ==================================================================
#define XSTRIDE3 148
#define SMEM_K3 ((64*XSTRIDE3 + 16*CROW) * 4)

__global__ __launch_bounds__(512) void k3_pairs(const float* __restrict__ feats)
{
    extern __shared__ float sm[];
    float* Xs = sm;                      // [64][148]
    float* Cs = sm + 64*XSTRIDE3;        // [16 np][2600]
    const int tid = threadIdx.x;
    const int cfg = blockIdx.x >> 1;
    const int rg  = blockIdx.x & 1;

    {
        const float4* src = (const float4*)(feats + (size_t)cfg*9216);
        for (int idx = tid; idx < 2304; idx += 512) {
            const int col = idx / 36, q = idx - col*36;
            *(float4*)(Xs + col*XSTRIDE3 + q*4) = src[idx];
        }
    }
    {
        const int npbase = cfg*32 + rg*16;
        for (int idx = tid; idx < 16*648; idx += 512) {
            const int np = idx / 648, q = idx - np*648;
            ((float4*)(Cs + np*CROW))[q] =
                ((const float4*)(g_C + (size_t)(npbase+np)*CROW))[q];
        }
    }
    __syncthreads();

    const int rp = tid >> 5;
    const int cg = tid & 31;
    const float* Crow = Cs + rp*CROW;

    u64t acc[2][9];
    #pragma unroll
    for (int c = 0; c < 2; c++)
        #pragma unroll
        for (int k = 0; k < 9; k++) acc[c][k] = 0ULL;

    #pragma unroll 2
    for (int q = 0; q < 36; q++) {
        const float4 xv0 = *(const float4*)(Xs + cg*XSTRIDE3 + q*4);
        const float4 xv1 = *(const float4*)(Xs + (cg+32)*XSTRIDE3 + q*4);
        u64t xp0[4], xp1[4];
        xp0[0] = pk2(xv0.x, xv0.x); xp0[1] = pk2(xv0.y, xv0.y);
        xp0[2] = pk2(xv0.z, xv0.z); xp0[3] = pk2(xv0.w, xv0.w);
        xp1[0] = pk2(xv1.x, xv1.x); xp1[1] = pk2(xv1.y, xv1.y);
        xp1[2] = pk2(xv1.z, xv1.z); xp1[3] = pk2(xv1.w, xv1.w);
        #pragma unroll
        for (int k = 0; k < 9; k++) {
            const double2* cp = (const double2*)(Crow + (k*144 + q*4)*2);
            const double2 d0 = cp[0], d1 = cp[1];
            const u64t c0 = __double_as_longlong(d0.x);
            const u64t c1 = __double_as_longlong(d0.y);
            const u64t c2 = __double_as_longlong(d1.x);
            const u64t c3 = __double_as_longlong(d1.y);
            fma2(acc[0][k], c0, xp0[0]); fma2(acc[0][k], c1, xp0[1]);
            fma2(acc[0][k], c2, xp0[2]); fma2(acc[0][k], c3, xp0[3]);
            fma2(acc[1][k], c0, xp1[0]); fma2(acc[1][k], c1, xp1[1]);
            fma2(acc[1][k], c2, xp1[2]); fma2(acc[1][k], c3, xp1[3]);
        }
    }

    const int row0 = rg*32 + 2*rp;
    const int e0 = cfg*4096 + row0*64 + cg;
    #pragma unroll
    for (int c = 0; c < 2; c++) {
        const int ec = e0 + c*32;
        #pragma unroll
        for (int k = 0; k < 9; k++) {
            float lo, hi; upk2(lo, hi, acc[c][k]);
            g_irr[(size_t)k*NPAIRS + ec]      = lo;
            g_irr[(size_t)k*NPAIRS + ec + 64] = hi;
        }
    }
}

// ==================================================================
// K4: cartesian change of basis + symmetrize; smem transpose tiles.
// Block = (cfg, 2x2 quadrant of 32x32 pairs): grid 256, 256 threads.
// ==================================================================
#define K4_A    0
#define K4_B    9216
#define K4_O    (9216 + 9504)
#define SMEM_K4 ((9216 + 9504 + 2304) * 4)

__global__ __launch_bounds__(256) void k4_cart(float* __restrict__ out, QParams qp)
{
    extern __shared__ float sm4[];
    float* A = sm4 + K4_A;
    float* B = sm4 + K4_B;
    float* obuf = sm4 + K4_O;
    const int tid = threadIdx.x;
    const int cfg = blockIdx.x >> 2;
    const int ib  = (blockIdx.x >> 1) & 1;
    const int jb  = blockIdx.x & 1;
    const int ebase = cfg*4096;

    for (int idx = tid; idx < 9216; idx += 256) {
        const int k = idx >> 10, p = idx & 1023, r = p >> 5, c = p & 31;
        A[idx] = g_irr[(size_t)k*NPAIRS + ebase + (ib*32+r)*64 + jb*32 + c];
        B[k*1056 + r*33 + c] =
            g_irr[(size_t)k*NPAIRS + ebase + (jb*32+r)*64 + ib*32 + c];
    }
    __syncthreads();

    for (int s = 0; s < 4; s++) {
        const int p = s*256 + tid;
        const int r = p >> 5, c = p & 31;
        float a[9], ap[9];
        #pragma unroll
        for (int k = 0; k < 9; k++) {
            a[k]  = A[k*1024 + p];
            ap[k] = B[k*1056 + c*33 + r];
        }
        #pragma unroll
        for (int ii = 0; ii < 3; ii++)
            #pragma unroll
            for (int jj = 0; jj < 3; jj++) {
                float sacc = 0.f;
                #pragma unroll
                for (int k = 0; k < 9; k++)
                    sacc += a[k]*qp.q[k*9 + ii*3 + jj] + ap[k]*qp.q[k*9 + jj*3 + ii];
                obuf[tid*9 + ii*3 + jj] = 0.5f * sacc;
            }
        __syncthreads();
        for (int idx = tid; idx < 576; idx += 256) {
            const int rl = idx / 72, q = idx - rl*72;
            ((float4*)(out + (size_t)(ebase + (ib*32 + s*8 + rl)*64 + jb*32)*9))[q] =
                ((const float4*)(obuf + rl*288))[q];
        }
        __syncthreads();
    }
}

// ==================================================================
// Host: real Wigner-3j (e3nn convention) + QCART + fold tables, per call.
// ==================================================================
static double h_fact(int n){ double r=1; for(int i=2;i<=n;i++) r*=i; return r; }

static double h_su2_cg(int j1,int m1,int j2,int m2,int j3,int m3){
    if (m3 != m1+m2) return 0.0;
    int vmin = std::max(std::max(-j1+j2+m3, -j1+m1), 0);
    int vmax = std::min(std::min(j2+j3+m1, j3-j1+j2), j3+m3);
    double C = sqrt((2.0*j3+1)*h_fact(j3+j1-j2)*h_fact(j3-j1+j2)*h_fact(j1+j2-j3)
               *h_fact(j3+m3)*h_fact(j3-m3)
               /(h_fact(j1+j2+j3+1)*h_fact(j1-m1)*h_fact(j1+m1)*h_fact(j2-m2)*h_fact(j2+m2)));
    double S = 0.0;
    for (int v = vmin; v <= vmax; v++) {
        double term = h_fact(j2+j3+m1-v)*h_fact(j1-m1+v)
                    /(h_fact(v)*h_fact(j3-j1+j2-v)*h_fact(j3+m3-v)*h_fact(v+j1-j2-m3));
        S += (((v+j2+m2) & 1) ? -1.0 : 1.0) * term;
    }
    return C*S;
}

typedef std::complex<double> cd;

static void h_qmat(int l, cd Q[5][5]){
    for (int i = 0; i < 5; i++) for (int j = 0; j < 5; j++) Q[i][j] = cd(0,0);
    const double s = 1.0/sqrt(2.0);
    for (int m = -l; m < 0; m++) {
        Q[l+m][l-m] = cd(s,0);
        Q[l+m][l+m] = cd(0,-s);
    }
    Q[l][l] = cd(1,0);
    for (int m = 1; m <= l; m++) {
        double sg = (m & 1) ? -1.0 : 1.0;
        Q[l+m][l+m] = cd(sg*s, 0);
        Q[l+m][l-m] = cd(0, sg*s);
    }
    cd f = (l==0) ? cd(1,0) : (l==1) ? cd(0,-1) : cd(-1,0);
    for (int i = 0; i < 5; i++) for (int j = 0; j < 5; j++) Q[i][j] *= f;
}

static void h_wigner3j(int l1,int l2,int l3, double W[5][5][5]){
    int d1 = 2*l1+1, d2 = 2*l2+1, d3 = 2*l3+1;
    double C[5][5][5] = {};
    for (int m1 = -l1; m1 <= l1; m1++)
        for (int m2 = -l2; m2 <= l2; m2++) {
            int m3 = m1+m2;
            if (m3 >= -l3 && m3 <= l3)
                C[l1+m1][l2+m2][l3+m3] = h_su2_cg(l1,m1,l2,m2,l3,m3);
        }
    cd Q1[5][5], Q2[5][5], Q3[5][5];
    h_qmat(l1,Q1); h_qmat(l2,Q2); h_qmat(l3,Q3);
    double nrm2 = 0.0;
    for (int j = 0; j < d1; j++)
      for (int lq = 0; lq < d2; lq++)
        for (int n = 0; n < d3; n++) {
            cd acc(0,0);
            for (int i = 0; i < d1; i++)
              for (int k = 0; k < d2; k++)
                for (int m = 0; m < d3; m++) {
                    double c = C[i][k][m];
                    if (c != 0.0) acc += Q1[i][j]*Q2[k][lq]*std::conj(Q3[m][n])*c;
                }
            W[j][lq][n] = acc.real();
            nrm2 += acc.real()*acc.real();
        }
    double inv = 1.0/sqrt(nrm2);
    for (int j = 0; j < d1; j++)
      for (int lq = 0; lq < d2; lq++)
        for (int n = 0; n < d3; n++) W[j][lq][n] *= inv;
}

static const int H_PL[15][3] = {{0,0,0},{1,1,0},{2,2,0},{0,1,1},{1,0,1},{1,1,1},
                                {1,2,1},{2,1,1},{2,2,1},{0,2,2},{2,0,2},{1,1,2},
                                {1,2,2},{2,1,2},{2,2,2}};
static const int H_W3OFF[15] = {0,1,10,35,44,53,80,125,170,245,270,295,340,415,490};

static void h_build_params(QParams& qp, FoldParams& fp){
    float w3[615];
    const double alpha[3] = { sqrt(1.0/768.0), sqrt(3.0/1536.0), sqrt(5.0/1536.0) };
    for (int p = 0; p < 15; p++) {
        int l1 = H_PL[p][0], l2 = H_PL[p][1], lo = H_PL[p][2];
        double W[5][5][5];
        h_wigner3j(l1,l2,lo,W);
        int jd = 2*l2+1, kd = 2*lo+1;
        for (int i = 0; i < 2*l1+1; i++)
          for (int j = 0; j < jd; j++)
            for (int k = 0; k < kd; k++)
                w3[H_W3OFF[p] + (i*jd+j)*kd + k] = (float)(alpha[lo]*W[i][j][k]);
    }
    int ko = 0;
    for (int l = 0; l <= 2; l++) {
        double W[5][5][5];
        h_wigner3j(1,1,l,W);
        double s = sqrt(2.0*l+1.0);
        for (int m = 0; m < 2*l+1; m++)
          for (int i = 0; i < 3; i++)
            for (int j = 0; j < 3; j++)
                qp.q[(ko+m)*9 + i*3 + j] = (float)(s*W[i][j][m]);
        ko += 2*l+1;
    }
    // cell-ordered fold coefficients, slices padded to multiples of 4.
    // cell order: lo-major (lo,l2) = (0,0)(0,1)(0,2)(1,0)(1,1)(1,2)(2,0)(2,1)(2,2)
    int nt = 0;
    for (int lo = 0; lo < 3; lo++) {
        const int kd = 2*lo+1;
        for (int l2 = 0; l2 < 3; l2++) {
            const int jd = 2*l2+1;
            const int S = (jd*kd + 3) & ~3;
            for (int p = 0; p < 15; p++) {
                if (H_PL[p][1] != l2 || H_PL[p][2] != lo) continue;
                for (int i = 0; i < 2*H_PL[p][0]+1; i++) {
                    for (int lin = 0; lin < S; lin++) {
                        if (lin < jd*kd) {
                            const int j = lin / kd, k = lin % kd;
                            fp.cf[nt++] = w3[H_W3OFF[p] + (i*jd + j)*kd + k];
                        } else fp.cf[nt++] = 0.0f;
                    }
                }
            }
        }
    }
    // nt == 724
}

// ==================================================================
extern "C" void kernel_launch(void* const* d_in, const int* in_sizes, int n_in,
                              void* d_out, int out_size)
{
    const float* feats = nullptr;
    const float* tpw   = nullptr;
    for (int i = 0; i < n_in; i++) {
        if (in_sizes[i] == NNODES*144)   feats = (const float*)d_in[i];
        else if (in_sizes[i] == 15*256)  tpw   = (const float*)d_in[i];
    }
    QParams qp; FoldParams fp;
    h_build_params(qp, fp);

    cudaFuncSetAttribute(k1_buildC, cudaFuncAttributeMaxDynamicSharedMemorySize, SMEM_K1);
    cudaFuncSetAttribute(k3_pairs,  cudaFuncAttributeMaxDynamicSharedMemorySize, SMEM_K3);
    cudaFuncSetAttribute(k4_cart,   cudaFuncAttributeMaxDynamicSharedMemorySize, SMEM_K4);

    k1_buildC<<<NNODES/8, 128, SMEM_K1>>>(feats, tpw, fp);
    k3_pairs<<<NCFG*2, 512, SMEM_K3>>>(feats);
    k4_cart<<<NCFG*4, 256, SMEM_K4>>>((float*)d_out, qp);
}